// round 13
// baseline (speedup 1.0000x reference)
#include <cuda_runtime.h>
#include <cuda_fp16.h>
#include <math.h>
#include <stdint.h>

// ---------------------------------------------------------------------------
// Mix_82360292868539 (R13): R12 + in-register quad-transpose epilogue
// (4x shfl.b64 per fragment row) -> 2x STG.128 instead of 4x scattered
// STG.64: halves epilogue store wavefronts without smem staging.
// ---------------------------------------------------------------------------

#define N_ROWS 8192
#define KD 64
#define SUB 512                         // subsample rows (stride 16)
#define NS ((unsigned long long)SUB * (unsigned long long)SUB)
#define NB_C 2048
#define COARSE_SCALE 4.0f
#define COARSE_W 0.25f

#define BT 128
#define KSB 144            // 128B row + 16B pad (conflict-free)
#define T_TILE (BT * KSB)              // 18432

// fused GEMM shared layout (bytes)
#define SM_SX  0
#define SM_SY  512
#define SM_A   1024
#define SM_B   (SM_A + T_TILE)         // 19456
#define SM_TOT (SM_B + T_TILE)         // 37888

// prep kernel (subhist role) shared layout
#define LDS_ 132
#define SH_SMEM (2*KD*LDS_*(int)sizeof(float) + NB_C*(int)sizeof(unsigned int))

#define N_SUB_CTAS  ((SUB/128)*(SUB/128))   // 16 -> blocks [0, 16)
#define N_CONV_CTAS 2048                    // blocks [16, 2064)

extern __shared__ char smem_raw[];

// ---- device scratch (zero-init at load; self-cleaned each run) -------------
__device__ __half g_xp[(size_t)N_ROWS * 64];     // hx, 1 MB
__device__ __half g_yp[(size_t)N_ROWS * 64];     // hy, 1 MB
__device__ float g_sqx[N_ROWS];
__device__ float g_sqy[N_ROWS];
__device__ unsigned int g_hist_c[NB_C];
__device__ unsigned int g_done;
__device__ float g_inv2sigma;

// ---- ptx helpers -----------------------------------------------------------
__device__ __forceinline__ uint32_t smem_u32(const void* p) {
    uint32_t a;
    asm("{ .reg .u64 t; cvta.to.shared.u64 t, %1; cvt.u32.u64 %0, t; }"
        : "=r"(a) : "l"(p));
    return a;
}

#define LDSM_X4(r0, r1, r2, r3, addr) \
    asm volatile("ldmatrix.sync.aligned.m8n8.x4.shared.b16 {%0,%1,%2,%3}, [%4];" \
        : "=r"(r0), "=r"(r1), "=r"(r2), "=r"(r3) : "r"(addr))

#define MMA16816F(c, a, b0, b1) \
    asm volatile("mma.sync.aligned.m16n8k16.row.col.f32.f16.f16.f32 " \
        "{%0,%1,%2,%3}, {%4,%5,%6,%7}, {%8,%9}, {%0,%1,%2,%3};" \
        : "+f"((c)[0]), "+f"((c)[1]), "+f"((c)[2]), "+f"((c)[3]) \
        : "r"((a)[0]), "r"((a)[1]), "r"((a)[2]), "r"((a)[3]), "r"(b0), "r"(b1))

// ---------------------------------------------------------------------------
// prep: blocks [0,16) = subsample pdist histogram (own norms, stride 16) with
// fused select + scratch cleanup in the last-done CTA; blocks [16,2064) =
// fp16 convert + row norms (one warp per row). Heavy CTAs scheduled first.
// ---------------------------------------------------------------------------
__global__ void __launch_bounds__(256)
prep_kernel(const float* __restrict__ X, const float* __restrict__ Y) {
    const int tid = threadIdx.x;
    const int bid = blockIdx.x;

    if (bid >= N_SUB_CTAS) {
        // ---- convert role --------------------------------------------------
        int gw = ((bid - N_SUB_CTAS) * 256 + tid) >> 5;
        int lane = tid & 31;
        if (gw >= 2 * N_ROWS) return;
        int isx = (gw < N_ROWS) ? 1 : 0;
        int r = isx ? gw : gw - N_ROWS;
        const float2 v = ((const float2*)((isx ? X : Y) + (size_t)r * KD))[lane];
        float s = v.x * v.x + v.y * v.y;
        #pragma unroll
        for (int o = 16; o; o >>= 1) s += __shfl_xor_sync(0xffffffffu, s, o);
        __half2 h = __floats2half2_rn(v.x, v.y);
        ((__half2*)((isx ? g_xp : g_yp) + (size_t)r * 64))[lane] = h;
        if (lane == 0) { if (isx) g_sqx[r] = s; else g_sqy[r] = s; }
        return;
    }

    // ---- subhist role ------------------------------------------------------
    float* smem = (float*)smem_raw;
    float* As = smem;                                   // [64][LDS_]
    float* Bs = smem + KD * LDS_;
    unsigned int* sh = (unsigned int*)(smem + 2 * KD * LDS_);

    const int bm = (bid >> 2) * 128;
    const int bn = (bid & 3) * 128;

    for (int i = tid; i < NB_C; i += 256) sh[i] = 0u;

    {
        const int c4 = tid >> 4;
        const int r0 = tid & 15;
        #pragma unroll
        for (int it = 0; it < 8; ++it) {
            int row = r0 + it * 16;
            const float4* Xr = (const float4*)(X + (size_t)(bm + row) * 16 * KD);
            const float4* Yr = (const float4*)(Y + (size_t)(bn + row) * 16 * KD);
            float4 v = Xr[c4];
            As[(c4 * 4 + 0) * LDS_ + row] = v.x;
            As[(c4 * 4 + 1) * LDS_ + row] = v.y;
            As[(c4 * 4 + 2) * LDS_ + row] = v.z;
            As[(c4 * 4 + 3) * LDS_ + row] = v.w;
            float4 w = Yr[c4];
            Bs[(c4 * 4 + 0) * LDS_ + row] = w.x;
            Bs[(c4 * 4 + 1) * LDS_ + row] = w.y;
            Bs[(c4 * 4 + 2) * LDS_ + row] = w.z;
            Bs[(c4 * 4 + 3) * LDS_ + row] = w.w;
        }
    }
    __syncthreads();

    const int tx = tid & 15, ty = tid >> 4;
    float acc[8][8];
    float sxr[8], syr[8];
    #pragma unroll
    for (int i = 0; i < 8; ++i) {
        sxr[i] = 0.0f; syr[i] = 0.0f;
        #pragma unroll
        for (int j = 0; j < 8; ++j) acc[i][j] = 0.0f;
    }

    #pragma unroll 8
    for (int k = 0; k < KD; ++k) {
        float4 a0 = *(const float4*)(As + k * LDS_ + ty * 8);
        float4 a1 = *(const float4*)(As + k * LDS_ + ty * 8 + 4);
        float4 b0 = *(const float4*)(Bs + k * LDS_ + tx * 8);
        float4 b1 = *(const float4*)(Bs + k * LDS_ + tx * 8 + 4);
        float a[8] = {a0.x, a0.y, a0.z, a0.w, a1.x, a1.y, a1.z, a1.w};
        float b[8] = {b0.x, b0.y, b0.z, b0.w, b1.x, b1.y, b1.z, b1.w};
        #pragma unroll
        for (int i = 0; i < 8; ++i) {
            sxr[i] = fmaf(a[i], a[i], sxr[i]);
            syr[i] = fmaf(b[i], b[i], syr[i]);
            #pragma unroll
            for (int j = 0; j < 8; ++j)
                acc[i][j] = fmaf(a[i], b[j], acc[i][j]);
        }
    }

    #pragma unroll
    for (int i = 0; i < 8; ++i)
        #pragma unroll
        for (int j = 0; j < 8; ++j) {
            float pd = sxr[i] + syr[j] - 2.0f * acc[i][j];
            int b = min(max((int)(pd * COARSE_SCALE), 0), NB_C - 1);
            atomicAdd(&sh[b], 1u);
        }

    __syncthreads();
    for (int i = tid; i < NB_C; i += 256) {
        unsigned int c = sh[i];
        if (c) atomicAdd(&g_hist_c[i], c);
    }

    // ---- last-CTA-done: fused select + scratch cleanup --------------------
    __shared__ unsigned int s_last;
    __threadfence();
    if (tid == 0) s_last = (atomicAdd(&g_done, 1u) == N_SUB_CTAS - 1u);
    __syncthreads();
    if (!s_last) return;

    __shared__ unsigned long long chunk[256];
    __shared__ float sv1, sv2;
    const int PER = NB_C / 256;
    unsigned long long s = 0;
    for (int u = 0; u < PER; ++u) s += g_hist_c[tid * PER + u];
    chunk[tid] = s;
    __syncthreads();
    #pragma unroll
    for (int off = 1; off < 256; off <<= 1) {
        unsigned long long add = (tid >= off) ? chunk[tid - off] : 0ull;
        __syncthreads();
        chunk[tid] += add;
        __syncthreads();
    }
    unsigned long long run = chunk[tid] - s;   // exclusive prefix
    const unsigned long long k1 = NS / 2 - 1, k2 = NS / 2;
    for (int u = 0; u < PER; ++u) {
        int b = tid * PER + u;
        unsigned long long c = g_hist_c[b];
        if (c) {
            if (k1 >= run && k1 < run + c)
                sv1 = ((float)b + ((float)(k1 - run) + 0.5f) / (float)c) * COARSE_W;
            if (k2 >= run && k2 < run + c)
                sv2 = ((float)b + ((float)(k2 - run) + 0.5f) / (float)c) * COARSE_W;
        }
        run += c;
    }
    __syncthreads();
    if (tid == 0) {
        float med = 0.5f * (sv1 + sv2);
        g_inv2sigma = logf((float)(N_ROWS + 1)) / med;
        g_done = 0u;                       // reset for graph replay
    }
    for (int i = tid; i < NB_C; i += 256) g_hist_c[i] = 0u;
}

// ---------------------------------------------------------------------------
// fp16 HMMA GEMM, 128x128 CTA tile, 8 warps (2M x 4N), warp tile 64x32, K=64.
// Fused epilogue with quad-transpose: each lane ends up owning 8 contiguous
// columns of its row -> 2x STG.128 per fragment row (half the wavefronts).
// ---------------------------------------------------------------------------
__global__ void __launch_bounds__(256, 2) gemm_fused_kernel(float* __restrict__ out) {
    char* smem = smem_raw;
    const uint32_t sb = smem_u32(smem);
    const int tid = threadIdx.x;
    const int wid = tid >> 5, lane = tid & 31;
    const int bm = blockIdx.y * BT, bn = blockIdx.x * BT;

    float* ssx = (float*)(smem + SM_SX);
    float* ssy = (float*)(smem + SM_SY);
    if (tid < BT) {
        ssx[tid] = g_sqx[bm + tid];
        ssy[tid] = g_sqy[bn + tid];
    }

    // A, B tiles: 128 rows x 8 uint4 each
    {
        const uint4* Ag = (const uint4*)(g_xp + (size_t)bm * 64);
        const uint4* Bg = (const uint4*)(g_yp + (size_t)bn * 64);
        #pragma unroll
        for (int it = 0; it < 4; ++it) {
            int i = tid + it * 256;        // 1024 uint4
            int r = i >> 3, c = i & 7;
            *(uint4*)(smem + SM_A + r * KSB + c * 16) = Ag[i];
            *(uint4*)(smem + SM_B + r * KSB + c * 16) = Bg[i];
        }
    }
    __syncthreads();

    const int wm = (wid & 1) * 64;
    const int wn = (wid >> 1) * 32;
    const int lrow = lane & 15;
    const int lcol = (lane >> 4) * 16;

    float acc[4][4][4];
    #pragma unroll
    for (int mt = 0; mt < 4; ++mt)
        #pragma unroll
        for (int nt = 0; nt < 4; ++nt)
            #pragma unroll
            for (int q = 0; q < 4; ++q) acc[mt][nt][q] = 0.0f;

    const uint32_t Abase = sb + SM_A + (wm + lrow) * KSB + lcol;
    const uint32_t Bbase = sb + SM_B + (wn + lrow) * KSB + lcol;

    #pragma unroll
    for (int kk = 0; kk < 4; ++kk) {       // 4 x k16 = K64
        const int kb = kk * 32;
        uint32_t b[2][4];
        #pragma unroll
        for (int np = 0; np < 2; ++np)
            LDSM_X4(b[np][0], b[np][1], b[np][2], b[np][3],
                    Bbase + np * (16 * KSB) + kb);
        uint32_t a[4][4];
        #pragma unroll
        for (int mt = 0; mt < 4; ++mt)
            LDSM_X4(a[mt][0], a[mt][1], a[mt][2], a[mt][3],
                    Abase + mt * (16 * KSB) + kb);
        #pragma unroll
        for (int mt = 0; mt < 4; ++mt)
            #pragma unroll
            for (int nt = 0; nt < 4; ++nt) {
                const int np = nt >> 1, h = nt & 1;
                MMA16816F(acc[mt][nt], a[mt], b[np][h], b[np][h + 2]);
            }
    }

    // fused epilogue with quad transpose
    const float inv2s = g_inv2sigma;
    const int qrow = lane >> 2;           // 0..7 (row within fragment)
    const int q    = lane & 3;            // 0..3 (quad position)
    const int qcol = q * 2;
    #pragma unroll
    for (int mt = 0; mt < 4; ++mt) {
        #pragma unroll
        for (int rs = 0; rs < 2; ++rs) {
            const int row = wm + mt * 16 + qrow + rs * 8;
            const float sx = ssx[row];
            double t[4];                   // float2 carriers, t[nt]
            #pragma unroll
            for (int nt = 0; nt < 4; ++nt) {
                const int col = wn + nt * 8 + qcol;
                const float v0 = acc[mt][nt][rs * 2 + 0];
                const float v1 = acc[mt][nt][rs * 2 + 1];
                float2 r;
                r.x = __expf(-(sx + ssy[col]     - 2.0f * v0) * inv2s) + 0.1f * v0 * v0;
                r.y = __expf(-(sx + ssy[col + 1] - 2.0f * v1) * inv2s) + 0.1f * v1 * v1;
                t[nt] = *(double*)&r;
            }
            // 4x4 transpose across the quad (stage xor2, then xor1):
            // after: lane q holds tile q, slot i = cols 2i..2i+1 of its row
            #pragma unroll
            for (int k = 0; k < 2; ++k) {
                double snd = (q & 2) ? t[k] : t[k + 2];
                double rcv = __shfl_xor_sync(0xffffffffu, snd, 2);
                if (q & 2) t[k] = rcv; else t[k + 2] = rcv;
            }
            #pragma unroll
            for (int k = 0; k < 4; k += 2) {
                double snd = (q & 1) ? t[k] : t[k + 1];
                double rcv = __shfl_xor_sync(0xffffffffu, snd, 1);
                if (q & 1) t[k] = rcv; else t[k + 1] = rcv;
            }
            float2 f0 = *(float2*)&t[0], f1 = *(float2*)&t[1];
            float2 f2 = *(float2*)&t[2], f3 = *(float2*)&t[3];
            float* gp = out + (size_t)(bm + row) * N_ROWS + bn + wn + q * 8;
            *(float4*)gp       = make_float4(f0.x, f0.y, f1.x, f1.y);
            *(float4*)(gp + 4) = make_float4(f2.x, f2.y, f3.x, f3.y);
        }
    }
}

// ---------------------------------------------------------------------------
extern "C" void kernel_launch(void* const* d_in, const int* in_sizes, int n_in,
                              void* d_out, int out_size) {
    const float* X = (const float*)d_in[0];
    const float* Y = (const float*)d_in[1];
    float* out = (float*)d_out;

    cudaFuncSetAttribute(gemm_fused_kernel, cudaFuncAttributeMaxDynamicSharedMemorySize,
                         SM_TOT);
    cudaFuncSetAttribute(prep_kernel, cudaFuncAttributeMaxDynamicSharedMemorySize,
                         SH_SMEM);

    prep_kernel<<<N_SUB_CTAS + N_CONV_CTAS, 256, SH_SMEM>>>(X, Y);
    gemm_fused_kernel<<<dim3(N_ROWS / BT, N_ROWS / BT), 256, SM_TOT>>>(out);
}

// round 14
// speedup vs baseline: 1.0598x; 1.0598x over previous
#include <cuda_runtime.h>
#include <cuda_fp16.h>
#include <math.h>
#include <stdint.h>

// ---------------------------------------------------------------------------
// Mix_82360292868539 (R14): R12 GEMM made PERSISTENT (304 CTAs, tile loop —
// kills ~13 scheduler wave transitions) + faster convert (2 rows/warp,
// float4) + removed redundant racy hist zeroing (scratch is self-cleaned).
// ---------------------------------------------------------------------------

#define N_ROWS 8192
#define KD 64
#define SUB 512                         // subsample rows (stride 16)
#define NS ((unsigned long long)SUB * (unsigned long long)SUB)
#define NB_C 2048
#define COARSE_SCALE 4.0f
#define COARSE_W 0.25f

#define BT 128
#define KSB 144            // 128B row + 16B pad (conflict-free)
#define T_TILE (BT * KSB)              // 18432
#define N_TILES ((N_ROWS/BT)*(N_ROWS/BT))   // 4096
#define G_PERSIST 304                   // 2 per SM (152 SMs on GB300)

// fused GEMM shared layout (bytes)
#define SM_SX  0
#define SM_SY  512
#define SM_A   1024
#define SM_B   (SM_A + T_TILE)         // 19456
#define SM_TOT (SM_B + T_TILE)         // 37888

// prep kernel (subhist role) shared layout
#define LDS_ 132
#define SH_SMEM (2*KD*LDS_*(int)sizeof(float) + NB_C*(int)sizeof(unsigned int))

#define N_SUB_CTAS  ((SUB/128)*(SUB/128))   // 16 -> blocks [0, 16)
#define N_CONV_CTAS 1024                    // blocks [16, 1040)

extern __shared__ char smem_raw[];

// ---- device scratch (zero-init at load; self-cleaned each run) -------------
__device__ __half g_xp[(size_t)N_ROWS * 64];     // hx, 1 MB
__device__ __half g_yp[(size_t)N_ROWS * 64];     // hy, 1 MB
__device__ float g_sqx[N_ROWS];
__device__ float g_sqy[N_ROWS];
__device__ unsigned int g_hist_c[NB_C];
__device__ unsigned int g_done;
__device__ float g_inv2sigma;

// ---- ptx helpers -----------------------------------------------------------
__device__ __forceinline__ uint32_t smem_u32(const void* p) {
    uint32_t a;
    asm("{ .reg .u64 t; cvta.to.shared.u64 t, %1; cvt.u32.u64 %0, t; }"
        : "=r"(a) : "l"(p));
    return a;
}

#define LDSM_X4(r0, r1, r2, r3, addr) \
    asm volatile("ldmatrix.sync.aligned.m8n8.x4.shared.b16 {%0,%1,%2,%3}, [%4];" \
        : "=r"(r0), "=r"(r1), "=r"(r2), "=r"(r3) : "r"(addr))

#define MMA16816F(c, a, b0, b1) \
    asm volatile("mma.sync.aligned.m16n8k16.row.col.f32.f16.f16.f32 " \
        "{%0,%1,%2,%3}, {%4,%5,%6,%7}, {%8,%9}, {%0,%1,%2,%3};" \
        : "+f"((c)[0]), "+f"((c)[1]), "+f"((c)[2]), "+f"((c)[3]) \
        : "r"((a)[0]), "r"((a)[1]), "r"((a)[2]), "r"((a)[3]), "r"(b0), "r"(b1))

// ---------------------------------------------------------------------------
// prep: blocks [0,16) = subsample pdist histogram (own norms, stride 16) with
// fused select + scratch cleanup in the last-done CTA; blocks [16,1040) =
// fp16 convert + row norms (one warp per TWO rows, float4 loads).
// ---------------------------------------------------------------------------
__global__ void __launch_bounds__(256)
prep_kernel(const float* __restrict__ X, const float* __restrict__ Y) {
    const int tid = threadIdx.x;
    const int bid = blockIdx.x;

    if (bid >= N_SUB_CTAS) {
        // ---- convert role: warp covers rows 2w, 2w+1 ----------------------
        const int lane = tid & 31;
        const int w = ((bid - N_SUB_CTAS) * 256 + tid) >> 5;   // 0..8191
        const int h = lane >> 4, l = lane & 15;
        const int gr = w * 2 + h;                              // 0..16383
        const int isx = (gr < N_ROWS) ? 1 : 0;
        const int r = isx ? gr : gr - N_ROWS;
        const float4 v = ((const float4*)((isx ? X : Y) + (size_t)r * KD))[l];
        float s = v.x * v.x + v.y * v.y + v.z * v.z + v.w * v.w;
        #pragma unroll
        for (int o = 8; o; o >>= 1) s += __shfl_xor_sync(0xffffffffu, s, o);
        __half2 h0 = __floats2half2_rn(v.x, v.y);
        __half2 h1 = __floats2half2_rn(v.z, v.w);
        uint2 pack;
        pack.x = *(uint32_t*)&h0;
        pack.y = *(uint32_t*)&h1;
        *(uint2*)((isx ? g_xp : g_yp) + (size_t)r * 64 + l * 4) = pack;
        if (l == 0) { if (isx) g_sqx[r] = s; else g_sqy[r] = s; }
        return;
    }

    // ---- subhist role ------------------------------------------------------
    float* smem = (float*)smem_raw;
    float* As = smem;                                   // [64][LDS_]
    float* Bs = smem + KD * LDS_;
    unsigned int* sh = (unsigned int*)(smem + 2 * KD * LDS_);

    const int bm = (bid >> 2) * 128;
    const int bn = (bid & 3) * 128;

    for (int i = tid; i < NB_C; i += 256) sh[i] = 0u;

    {
        const int c4 = tid >> 4;
        const int r0 = tid & 15;
        #pragma unroll
        for (int it = 0; it < 8; ++it) {
            int row = r0 + it * 16;
            const float4* Xr = (const float4*)(X + (size_t)(bm + row) * 16 * KD);
            const float4* Yr = (const float4*)(Y + (size_t)(bn + row) * 16 * KD);
            float4 v = Xr[c4];
            As[(c4 * 4 + 0) * LDS_ + row] = v.x;
            As[(c4 * 4 + 1) * LDS_ + row] = v.y;
            As[(c4 * 4 + 2) * LDS_ + row] = v.z;
            As[(c4 * 4 + 3) * LDS_ + row] = v.w;
            float4 w = Yr[c4];
            Bs[(c4 * 4 + 0) * LDS_ + row] = w.x;
            Bs[(c4 * 4 + 1) * LDS_ + row] = w.y;
            Bs[(c4 * 4 + 2) * LDS_ + row] = w.z;
            Bs[(c4 * 4 + 3) * LDS_ + row] = w.w;
        }
    }
    __syncthreads();

    const int tx = tid & 15, ty = tid >> 4;
    float acc[8][8];
    float sxr[8], syr[8];
    #pragma unroll
    for (int i = 0; i < 8; ++i) {
        sxr[i] = 0.0f; syr[i] = 0.0f;
        #pragma unroll
        for (int j = 0; j < 8; ++j) acc[i][j] = 0.0f;
    }

    #pragma unroll 8
    for (int k = 0; k < KD; ++k) {
        float4 a0 = *(const float4*)(As + k * LDS_ + ty * 8);
        float4 a1 = *(const float4*)(As + k * LDS_ + ty * 8 + 4);
        float4 b0 = *(const float4*)(Bs + k * LDS_ + tx * 8);
        float4 b1 = *(const float4*)(Bs + k * LDS_ + tx * 8 + 4);
        float a[8] = {a0.x, a0.y, a0.z, a0.w, a1.x, a1.y, a1.z, a1.w};
        float b[8] = {b0.x, b0.y, b0.z, b0.w, b1.x, b1.y, b1.z, b1.w};
        #pragma unroll
        for (int i = 0; i < 8; ++i) {
            sxr[i] = fmaf(a[i], a[i], sxr[i]);
            syr[i] = fmaf(b[i], b[i], syr[i]);
            #pragma unroll
            for (int j = 0; j < 8; ++j)
                acc[i][j] = fmaf(a[i], b[j], acc[i][j]);
        }
    }

    #pragma unroll
    for (int i = 0; i < 8; ++i)
        #pragma unroll
        for (int j = 0; j < 8; ++j) {
            float pd = sxr[i] + syr[j] - 2.0f * acc[i][j];
            int b = min(max((int)(pd * COARSE_SCALE), 0), NB_C - 1);
            atomicAdd(&sh[b], 1u);
        }

    __syncthreads();
    for (int i = tid; i < NB_C; i += 256) {
        unsigned int c = sh[i];
        if (c) atomicAdd(&g_hist_c[i], c);
    }

    // ---- last-CTA-done: fused select + scratch cleanup --------------------
    __shared__ unsigned int s_last;
    __threadfence();
    if (tid == 0) s_last = (atomicAdd(&g_done, 1u) == N_SUB_CTAS - 1u);
    __syncthreads();
    if (!s_last) return;

    __shared__ unsigned long long chunk[256];
    __shared__ float sv1, sv2;
    const int PER = NB_C / 256;
    unsigned long long s = 0;
    for (int u = 0; u < PER; ++u) s += g_hist_c[tid * PER + u];
    chunk[tid] = s;
    __syncthreads();
    #pragma unroll
    for (int off = 1; off < 256; off <<= 1) {
        unsigned long long add = (tid >= off) ? chunk[tid - off] : 0ull;
        __syncthreads();
        chunk[tid] += add;
        __syncthreads();
    }
    unsigned long long run = chunk[tid] - s;   // exclusive prefix
    const unsigned long long k1 = NS / 2 - 1, k2 = NS / 2;
    for (int u = 0; u < PER; ++u) {
        int b = tid * PER + u;
        unsigned long long c = g_hist_c[b];
        if (c) {
            if (k1 >= run && k1 < run + c)
                sv1 = ((float)b + ((float)(k1 - run) + 0.5f) / (float)c) * COARSE_W;
            if (k2 >= run && k2 < run + c)
                sv2 = ((float)b + ((float)(k2 - run) + 0.5f) / (float)c) * COARSE_W;
        }
        run += c;
    }
    __syncthreads();
    if (tid == 0) {
        float med = 0.5f * (sv1 + sv2);
        g_inv2sigma = logf((float)(N_ROWS + 1)) / med;
        g_done = 0u;                       // reset for graph replay
    }
    for (int i = tid; i < NB_C; i += 256) g_hist_c[i] = 0u;
}

// ---------------------------------------------------------------------------
// PERSISTENT fp16 HMMA GEMM: 304 CTAs loop over 4096 tiles (128x128, 8 warps,
// warp tile 64x32, K=64). Fused epilogue: out = exp(-pd*inv2s) + 0.1*inner^2.
// ---------------------------------------------------------------------------
__global__ void __launch_bounds__(256, 2) gemm_fused_kernel(float* __restrict__ out) {
    char* smem = smem_raw;
    const uint32_t sb = smem_u32(smem);
    const int tid = threadIdx.x;
    const int wid = tid >> 5, lane = tid & 31;

    float* ssx = (float*)(smem + SM_SX);
    float* ssy = (float*)(smem + SM_SY);

    const int wm = (wid & 1) * 64;
    const int wn = (wid >> 1) * 32;
    const int lrow = lane & 15;
    const int lcol = (lane >> 4) * 16;
    const int qrow = lane >> 2;
    const int qcol = (lane & 3) * 2;
    const float inv2s = g_inv2sigma;

    const uint32_t Abase = sb + SM_A + (wm + lrow) * KSB + lcol;
    const uint32_t Bbase = sb + SM_B + (wn + lrow) * KSB + lcol;

    for (int tile = blockIdx.x; tile < N_TILES; tile += G_PERSIST) {
        const int bm = (tile >> 6) * BT;
        const int bn = (tile & 63) * BT;

        __syncthreads();   // previous iteration's smem readers are done
        if (tid < BT) {
            ssx[tid] = g_sqx[bm + tid];
            ssy[tid] = g_sqy[bn + tid];
        }
        {
            const uint4* Ag = (const uint4*)(g_xp + (size_t)bm * 64);
            const uint4* Bg = (const uint4*)(g_yp + (size_t)bn * 64);
            #pragma unroll
            for (int it = 0; it < 4; ++it) {
                int i = tid + it * 256;        // 1024 uint4
                int r = i >> 3, c = i & 7;
                *(uint4*)(smem + SM_A + r * KSB + c * 16) = Ag[i];
                *(uint4*)(smem + SM_B + r * KSB + c * 16) = Bg[i];
            }
        }
        __syncthreads();

        float acc[4][4][4];
        #pragma unroll
        for (int mt = 0; mt < 4; ++mt)
            #pragma unroll
            for (int nt = 0; nt < 4; ++nt)
                #pragma unroll
                for (int q = 0; q < 4; ++q) acc[mt][nt][q] = 0.0f;

        #pragma unroll
        for (int kk = 0; kk < 4; ++kk) {       // 4 x k16 = K64
            const int kb = kk * 32;
            uint32_t b[2][4];
            #pragma unroll
            for (int np = 0; np < 2; ++np)
                LDSM_X4(b[np][0], b[np][1], b[np][2], b[np][3],
                        Bbase + np * (16 * KSB) + kb);
            uint32_t a[4][4];
            #pragma unroll
            for (int mt = 0; mt < 4; ++mt)
                LDSM_X4(a[mt][0], a[mt][1], a[mt][2], a[mt][3],
                        Abase + mt * (16 * KSB) + kb);
            #pragma unroll
            for (int mt = 0; mt < 4; ++mt)
                #pragma unroll
                for (int nt = 0; nt < 4; ++nt) {
                    const int np = nt >> 1, h = nt & 1;
                    MMA16816F(acc[mt][nt], a[mt], b[np][h], b[np][h + 2]);
                }
        }

        // fused epilogue
        #pragma unroll
        for (int mt = 0; mt < 4; ++mt) {
            #pragma unroll
            for (int rs = 0; rs < 2; ++rs) {
                const int row = wm + mt * 16 + qrow + rs * 8;
                const float sx = ssx[row];
                float* gout = out + (size_t)(bm + row) * N_ROWS + bn;
                #pragma unroll
                for (int nt = 0; nt < 4; ++nt) {
                    const int col = wn + nt * 8 + qcol;
                    const float v0 = acc[mt][nt][rs * 2 + 0];
                    const float v1 = acc[mt][nt][rs * 2 + 1];
                    float r0 = __expf(-(sx + ssy[col]     - 2.0f * v0) * inv2s) + 0.1f * v0 * v0;
                    float r1 = __expf(-(sx + ssy[col + 1] - 2.0f * v1) * inv2s) + 0.1f * v1 * v1;
                    *(float2*)(gout + col) = make_float2(r0, r1);
                }
            }
        }
    }
}

// ---------------------------------------------------------------------------
extern "C" void kernel_launch(void* const* d_in, const int* in_sizes, int n_in,
                              void* d_out, int out_size) {
    const float* X = (const float*)d_in[0];
    const float* Y = (const float*)d_in[1];
    float* out = (float*)d_out;

    cudaFuncSetAttribute(gemm_fused_kernel, cudaFuncAttributeMaxDynamicSharedMemorySize,
                         SM_TOT);
    cudaFuncSetAttribute(prep_kernel, cudaFuncAttributeMaxDynamicSharedMemorySize,
                         SH_SMEM);

    prep_kernel<<<N_SUB_CTAS + N_CONV_CTAS, 256, SH_SMEM>>>(X, Y);
    gemm_fused_kernel<<<G_PERSIST, 256, SM_TOT>>>(out);
}

// round 15
// speedup vs baseline: 1.1417x; 1.0773x over previous
#include <cuda_runtime.h>
#include <cuda_fp16.h>
#include <math.h>
#include <stdint.h>

// ---------------------------------------------------------------------------
// Mix_82360292868539 (R15): R14 + subhist split into 64 CTAs of 64x64 tiles
// (was 16 CTAs of 128x128 — the 10us prep long pole). Same SUB=512 sample
// set, same binning -> bit-identical sigma.
// ---------------------------------------------------------------------------

#define N_ROWS 8192
#define KD 64
#define SUB 512                         // subsample rows (stride 16)
#define NS ((unsigned long long)SUB * (unsigned long long)SUB)
#define NB_C 2048
#define COARSE_SCALE 4.0f
#define COARSE_W 0.25f

#define BT 128
#define KSB 144            // 128B row + 16B pad (conflict-free)
#define T_TILE (BT * KSB)              // 18432
#define N_TILES ((N_ROWS/BT)*(N_ROWS/BT))   // 4096
#define G_PERSIST 304                   // 2 per SM (152 SMs on GB300)

// fused GEMM shared layout (bytes)
#define SM_SX  0
#define SM_SY  512
#define SM_A   1024
#define SM_B   (SM_A + T_TILE)         // 19456
#define SM_TOT (SM_B + T_TILE)         // 37888

// prep kernel (subhist role) shared layout: 64x64 tiles
#define LDS2 68
#define SH_SMEM (2*KD*LDS2*(int)sizeof(float) + NB_C*(int)sizeof(unsigned int))

#define N_SUB_CTAS  64                      // 8x8 grid of 64x64 tiles
#define N_CONV_CTAS 1024                    // blocks [64, 1088)

extern __shared__ char smem_raw[];

// ---- device scratch (zero-init at load; self-cleaned each run) -------------
__device__ __half g_xp[(size_t)N_ROWS * 64];     // hx, 1 MB
__device__ __half g_yp[(size_t)N_ROWS * 64];     // hy, 1 MB
__device__ float g_sqx[N_ROWS];
__device__ float g_sqy[N_ROWS];
__device__ unsigned int g_hist_c[NB_C];
__device__ unsigned int g_done;
__device__ float g_inv2sigma;

// ---- ptx helpers -----------------------------------------------------------
__device__ __forceinline__ uint32_t smem_u32(const void* p) {
    uint32_t a;
    asm("{ .reg .u64 t; cvta.to.shared.u64 t, %1; cvt.u32.u64 %0, t; }"
        : "=r"(a) : "l"(p));
    return a;
}

#define LDSM_X4(r0, r1, r2, r3, addr) \
    asm volatile("ldmatrix.sync.aligned.m8n8.x4.shared.b16 {%0,%1,%2,%3}, [%4];" \
        : "=r"(r0), "=r"(r1), "=r"(r2), "=r"(r3) : "r"(addr))

#define MMA16816F(c, a, b0, b1) \
    asm volatile("mma.sync.aligned.m16n8k16.row.col.f32.f16.f16.f32 " \
        "{%0,%1,%2,%3}, {%4,%5,%6,%7}, {%8,%9}, {%0,%1,%2,%3};" \
        : "+f"((c)[0]), "+f"((c)[1]), "+f"((c)[2]), "+f"((c)[3]) \
        : "r"((a)[0]), "r"((a)[1]), "r"((a)[2]), "r"((a)[3]), "r"(b0), "r"(b1))

// ---------------------------------------------------------------------------
// prep: blocks [0,64) = subsample pdist histogram on 64x64 tiles (own norms,
// stride 16) with fused select + scratch cleanup in the last-done CTA;
// blocks [64,1088) = fp16 convert + row norms (one warp per two rows).
// ---------------------------------------------------------------------------
__global__ void __launch_bounds__(256)
prep_kernel(const float* __restrict__ X, const float* __restrict__ Y) {
    const int tid = threadIdx.x;
    const int bid = blockIdx.x;

    if (bid >= N_SUB_CTAS) {
        // ---- convert role: warp covers rows 2w, 2w+1 ----------------------
        const int lane = tid & 31;
        const int w = ((bid - N_SUB_CTAS) * 256 + tid) >> 5;   // 0..8191
        const int h = lane >> 4, l = lane & 15;
        const int gr = w * 2 + h;                              // 0..16383
        const int isx = (gr < N_ROWS) ? 1 : 0;
        const int r = isx ? gr : gr - N_ROWS;
        const float4 v = ((const float4*)((isx ? X : Y) + (size_t)r * KD))[l];
        float s = v.x * v.x + v.y * v.y + v.z * v.z + v.w * v.w;
        #pragma unroll
        for (int o = 8; o; o >>= 1) s += __shfl_xor_sync(0xffffffffu, s, o);
        __half2 h0 = __floats2half2_rn(v.x, v.y);
        __half2 h1 = __floats2half2_rn(v.z, v.w);
        uint2 pack;
        pack.x = *(uint32_t*)&h0;
        pack.y = *(uint32_t*)&h1;
        *(uint2*)((isx ? g_xp : g_yp) + (size_t)r * 64 + l * 4) = pack;
        if (l == 0) { if (isx) g_sqx[r] = s; else g_sqy[r] = s; }
        return;
    }

    // ---- subhist role: 64x64 tile ------------------------------------------
    float* smem = (float*)smem_raw;
    float* As = smem;                                   // [64][LDS2] transposed
    float* Bs = smem + KD * LDS2;
    unsigned int* sh = (unsigned int*)(smem + 2 * KD * LDS2);

    const int bm = (bid >> 3) * 64;       // subsample-row base (x side)
    const int bn = (bid & 7) * 64;        // subsample-row base (y side)

    for (int i = tid; i < NB_C; i += 256) sh[i] = 0u;

    {
        const int c4 = tid & 15;          // which float4 of the 64-wide row
        const int r0 = tid >> 4;          // 0..15
        #pragma unroll
        for (int it = 0; it < 4; ++it) {
            int row = r0 + it * 16;       // 0..63
            const float4 v = ((const float4*)(X + (size_t)(bm + row) * 16 * KD))[c4];
            As[(c4 * 4 + 0) * LDS2 + row] = v.x;
            As[(c4 * 4 + 1) * LDS2 + row] = v.y;
            As[(c4 * 4 + 2) * LDS2 + row] = v.z;
            As[(c4 * 4 + 3) * LDS2 + row] = v.w;
            const float4 w = ((const float4*)(Y + (size_t)(bn + row) * 16 * KD))[c4];
            Bs[(c4 * 4 + 0) * LDS2 + row] = w.x;
            Bs[(c4 * 4 + 1) * LDS2 + row] = w.y;
            Bs[(c4 * 4 + 2) * LDS2 + row] = w.z;
            Bs[(c4 * 4 + 3) * LDS2 + row] = w.w;
        }
    }
    __syncthreads();

    const int tx = tid & 15, ty = tid >> 4;
    float acc[4][4];
    float sxr[4], syr[4];
    #pragma unroll
    for (int i = 0; i < 4; ++i) {
        sxr[i] = 0.0f; syr[i] = 0.0f;
        #pragma unroll
        for (int j = 0; j < 4; ++j) acc[i][j] = 0.0f;
    }

    #pragma unroll 8
    for (int k = 0; k < KD; ++k) {
        float4 a4 = *(const float4*)(As + k * LDS2 + ty * 4);
        float4 b4 = *(const float4*)(Bs + k * LDS2 + tx * 4);
        float a[4] = {a4.x, a4.y, a4.z, a4.w};
        float b[4] = {b4.x, b4.y, b4.z, b4.w};
        #pragma unroll
        for (int i = 0; i < 4; ++i) {
            sxr[i] = fmaf(a[i], a[i], sxr[i]);
            syr[i] = fmaf(b[i], b[i], syr[i]);
            #pragma unroll
            for (int j = 0; j < 4; ++j)
                acc[i][j] = fmaf(a[i], b[j], acc[i][j]);
        }
    }

    #pragma unroll
    for (int i = 0; i < 4; ++i)
        #pragma unroll
        for (int j = 0; j < 4; ++j) {
            float pd = sxr[i] + syr[j] - 2.0f * acc[i][j];
            int b = min(max((int)(pd * COARSE_SCALE), 0), NB_C - 1);
            atomicAdd(&sh[b], 1u);
        }

    __syncthreads();
    for (int i = tid; i < NB_C; i += 256) {
        unsigned int c = sh[i];
        if (c) atomicAdd(&g_hist_c[i], c);
    }

    // ---- last-CTA-done: fused select + scratch cleanup --------------------
    __shared__ unsigned int s_last;
    __threadfence();
    if (tid == 0) s_last = (atomicAdd(&g_done, 1u) == N_SUB_CTAS - 1u);
    __syncthreads();
    if (!s_last) return;

    __shared__ unsigned long long chunk[256];
    __shared__ float sv1, sv2;
    const int PER = NB_C / 256;
    unsigned long long s = 0;
    for (int u = 0; u < PER; ++u) s += g_hist_c[tid * PER + u];
    chunk[tid] = s;
    __syncthreads();
    #pragma unroll
    for (int off = 1; off < 256; off <<= 1) {
        unsigned long long add = (tid >= off) ? chunk[tid - off] : 0ull;
        __syncthreads();
        chunk[tid] += add;
        __syncthreads();
    }
    unsigned long long run = chunk[tid] - s;   // exclusive prefix
    const unsigned long long k1 = NS / 2 - 1, k2 = NS / 2;
    for (int u = 0; u < PER; ++u) {
        int b = tid * PER + u;
        unsigned long long c = g_hist_c[b];
        if (c) {
            if (k1 >= run && k1 < run + c)
                sv1 = ((float)b + ((float)(k1 - run) + 0.5f) / (float)c) * COARSE_W;
            if (k2 >= run && k2 < run + c)
                sv2 = ((float)b + ((float)(k2 - run) + 0.5f) / (float)c) * COARSE_W;
        }
        run += c;
    }
    __syncthreads();
    if (tid == 0) {
        float med = 0.5f * (sv1 + sv2);
        g_inv2sigma = logf((float)(N_ROWS + 1)) / med;
        g_done = 0u;                       // reset for graph replay
    }
    for (int i = tid; i < NB_C; i += 256) g_hist_c[i] = 0u;
}

// ---------------------------------------------------------------------------
// PERSISTENT fp16 HMMA GEMM: 304 CTAs loop over 4096 tiles (128x128, 8 warps,
// warp tile 64x32, K=64). Fused epilogue: out = exp(-pd*inv2s) + 0.1*inner^2.
// ---------------------------------------------------------------------------
__global__ void __launch_bounds__(256, 2) gemm_fused_kernel(float* __restrict__ out) {
    char* smem = smem_raw;
    const uint32_t sb = smem_u32(smem);
    const int tid = threadIdx.x;
    const int wid = tid >> 5, lane = tid & 31;

    float* ssx = (float*)(smem + SM_SX);
    float* ssy = (float*)(smem + SM_SY);

    const int wm = (wid & 1) * 64;
    const int wn = (wid >> 1) * 32;
    const int lrow = lane & 15;
    const int lcol = (lane >> 4) * 16;
    const int qrow = lane >> 2;
    const int qcol = (lane & 3) * 2;
    const float inv2s = g_inv2sigma;

    const uint32_t Abase = sb + SM_A + (wm + lrow) * KSB + lcol;
    const uint32_t Bbase = sb + SM_B + (wn + lrow) * KSB + lcol;

    for (int tile = blockIdx.x; tile < N_TILES; tile += G_PERSIST) {
        const int bm = (tile >> 6) * BT;
        const int bn = (tile & 63) * BT;

        __syncthreads();   // previous iteration's smem readers are done
        if (tid < BT) {
            ssx[tid] = g_sqx[bm + tid];
            ssy[tid] = g_sqy[bn + tid];
        }
        {
            const uint4* Ag = (const uint4*)(g_xp + (size_t)bm * 64);
            const uint4* Bg = (const uint4*)(g_yp + (size_t)bn * 64);
            #pragma unroll
            for (int it = 0; it < 4; ++it) {
                int i = tid + it * 256;        // 1024 uint4
                int r = i >> 3, c = i & 7;
                *(uint4*)(smem + SM_A + r * KSB + c * 16) = Ag[i];
                *(uint4*)(smem + SM_B + r * KSB + c * 16) = Bg[i];
            }
        }
        __syncthreads();

        float acc[4][4][4];
        #pragma unroll
        for (int mt = 0; mt < 4; ++mt)
            #pragma unroll
            for (int nt = 0; nt < 4; ++nt)
                #pragma unroll
                for (int q = 0; q < 4; ++q) acc[mt][nt][q] = 0.0f;

        #pragma unroll
        for (int kk = 0; kk < 4; ++kk) {       // 4 x k16 = K64
            const int kb = kk * 32;
            uint32_t b[2][4];
            #pragma unroll
            for (int np = 0; np < 2; ++np)
                LDSM_X4(b[np][0], b[np][1], b[np][2], b[np][3],
                        Bbase + np * (16 * KSB) + kb);
            uint32_t a[4][4];
            #pragma unroll
            for (int mt = 0; mt < 4; ++mt)
                LDSM_X4(a[mt][0], a[mt][1], a[mt][2], a[mt][3],
                        Abase + mt * (16 * KSB) + kb);
            #pragma unroll
            for (int mt = 0; mt < 4; ++mt)
                #pragma unroll
                for (int nt = 0; nt < 4; ++nt) {
                    const int np = nt >> 1, h = nt & 1;
                    MMA16816F(acc[mt][nt], a[mt], b[np][h], b[np][h + 2]);
                }
        }

        // fused epilogue
        #pragma unroll
        for (int mt = 0; mt < 4; ++mt) {
            #pragma unroll
            for (int rs = 0; rs < 2; ++rs) {
                const int row = wm + mt * 16 + qrow + rs * 8;
                const float sx = ssx[row];
                float* gout = out + (size_t)(bm + row) * N_ROWS + bn;
                #pragma unroll
                for (int nt = 0; nt < 4; ++nt) {
                    const int col = wn + nt * 8 + qcol;
                    const float v0 = acc[mt][nt][rs * 2 + 0];
                    const float v1 = acc[mt][nt][rs * 2 + 1];
                    float r0 = __expf(-(sx + ssy[col]     - 2.0f * v0) * inv2s) + 0.1f * v0 * v0;
                    float r1 = __expf(-(sx + ssy[col + 1] - 2.0f * v1) * inv2s) + 0.1f * v1 * v1;
                    *(float2*)(gout + col) = make_float2(r0, r1);
                }
            }
        }
    }
}

// ---------------------------------------------------------------------------
extern "C" void kernel_launch(void* const* d_in, const int* in_sizes, int n_in,
                              void* d_out, int out_size) {
    const float* X = (const float*)d_in[0];
    const float* Y = (const float*)d_in[1];
    float* out = (float*)d_out;

    cudaFuncSetAttribute(gemm_fused_kernel, cudaFuncAttributeMaxDynamicSharedMemorySize,
                         SM_TOT);
    cudaFuncSetAttribute(prep_kernel, cudaFuncAttributeMaxDynamicSharedMemorySize,
                         SH_SMEM);

    prep_kernel<<<N_SUB_CTAS + N_CONV_CTAS, 256, SH_SMEM>>>(X, Y);
    gemm_fused_kernel<<<G_PERSIST, 256, SM_TOT>>>(out);
}